// round 7
// baseline (speedup 1.0000x reference)
#include <cuda_runtime.h>
#include <cuda_fp16.h>
#include <cstdint>

#define NIMG 8
#define CDIM 512
#define HDIM 32
#define WDIM 32
#define ODIM 512
#define KW   5
#define HH   28
#define WWN  28
#define NWIN (NIMG*HH*WWN)      // 6272
#define PIX_PER_IMG (HH*WWN)    // 784
#define LNEPS 1e-5f

// ---------------- scratch (no allocations allowed) ----------------
__device__ __half g_xa_h[(size_t)NWIN * CDIM];   // 6.4MB
__device__ __half g_pw_h[ODIM * CDIM];

__device__ __forceinline__ uint32_t s2u(const void* p) {
    return (uint32_t)__cvta_generic_to_shared(p);
}
__device__ __forceinline__ void ldmx4(uint32_t r[4], uint32_t a) {
    asm volatile("ldmatrix.sync.aligned.m8n8.x4.shared.b16 {%0,%1,%2,%3}, [%4];"
        : "=r"(r[0]), "=r"(r[1]), "=r"(r[2]), "=r"(r[3]) : "r"(a));
}
__device__ __forceinline__ void mma16816(float d[4], const uint32_t a[4], const uint32_t b[2]) {
    asm volatile("mma.sync.aligned.m16n8k16.row.col.f32.f16.f16.f32 "
        "{%0,%1,%2,%3}, {%4,%5,%6,%7}, {%8,%9}, {%0,%1,%2,%3};"
        : "+f"(d[0]), "+f"(d[1]), "+f"(d[2]), "+f"(d[3])
        : "r"(a[0]), "r"(a[1]), "r"(a[2]), "r"(a[3]), "r"(b[0]), "r"(b[1]));
}
__device__ __forceinline__ void cpasync16(uint32_t s, const void* g) {
    asm volatile("cp.async.cg.shared.global [%0], [%1], 16;" :: "r"(s), "l"(g));
}
#define CP_COMMIT() asm volatile("cp.async.commit_group;" ::: "memory")
#define CP_WAIT1()  asm volatile("cp.async.wait_group 1;" ::: "memory")

// ---------------------------------------------------------------------------
// prep: proj_w -> fp16  (4 elems/thread)
// ---------------------------------------------------------------------------
__global__ void prep_w_kernel(const float* __restrict__ pw) {
    int i = (blockIdx.x * 256 + threadIdx.x) * 4;   // < 262144
    float4 v = *(const float4*)(pw + i);
    __half2 a; a.x = __float2half(v.x); a.y = __float2half(v.y);
    __half2 b; b.x = __float2half(v.z); b.y = __float2half(v.w);
    *(__half2*)(g_pw_h + i)     = a;
    *(__half2*)(g_pw_h + i + 2) = b;
}

// ---------------------------------------------------------------------------
// K12 (fused): one block per 8x11 pixel patch (4x7 windows), 128 threads.
//   Pass 1: stream 88 rows of x once; compute 88 score dots (warp reduce)
//           AND park rows in smem as fp16.
//   Then:   LN + softmax for the 28 windows.
//   Pass 2: weighted aggregation from smem, write fp16 agg to gmem.
// ---------------------------------------------------------------------------
#define SX_B   (88*512*2)            // 90112
#define SRAW_O SX_B                  // 88*4 floats = 1408
#define SFIN_O (SRAW_O + 1408)       // 88 floats  = 352
#define WGT_O  (SFIN_O + 352)        // 28*25 floats = 2800
#define FUSED_SMEM (WGT_O + 2800)    // 94672

__global__ __launch_bounds__(128)
void fused_attn_kernel(const float* __restrict__ x,
                       const float* __restrict__ sw,
                       const float* __restrict__ sb,
                       const float* __restrict__ lnw,
                       const float* __restrict__ lnb) {
    extern __shared__ char dsm[];
    __half2* sx  = (__half2*)dsm;                    // [row][256] half2
    float* sraw  = (float*)(dsm + SRAW_O);           // [row][4]
    float* sfin  = (float*)(dsm + SFIN_O);           // [row]
    float (*wgt)[25] = (float(*)[25])(dsm + WGT_O);  // [28][25]

    const int b  = blockIdx.x;           // 224
    const int n  = b / 28;
    const int rb = b % 28;
    const int hh0 = (rb >> 2) * 4;
    const int ww0 = (rb & 3) * 7;
    const int t = threadIdx.x;
    const int wid = t >> 5, lane = t & 31;

    const float4 swv = __ldg((const float4*)sw + t);

    // ---- pass 1: load rows, score partials, park fp16 in smem ----
#pragma unroll
    for (int ki = 0; ki < 8; ki++) {
        const float4* rbp = (const float4*)(x +
            ((size_t)((n*HDIM + hh0 + ki)*WDIM + ww0)) * CDIM) + t;
        float4 v[11];
#pragma unroll
        for (int kj = 0; kj < 11; kj++) v[kj] = __ldg(rbp + kj*(CDIM/4));
#pragma unroll
        for (int kj = 0; kj < 11; kj++) {
            int row = ki*11 + kj;
            float p = v[kj].x*swv.x + v[kj].y*swv.y + v[kj].z*swv.z + v[kj].w*swv.w;
#pragma unroll
            for (int o = 16; o; o >>= 1) p += __shfl_xor_sync(0xffffffffu, p, o);
            if (lane == 0) sraw[row*4 + wid] = p;
            __half2 a; a.x = __float2half(v[kj].x); a.y = __float2half(v[kj].y);
            __half2 c; c.x = __float2half(v[kj].z); c.y = __float2half(v[kj].w);
            sx[row*256 + 2*t]     = a;
            sx[row*256 + 2*t + 1] = c;
        }
    }
    __syncthreads();
    if (t < 88)
        sfin[t] = sraw[t*4] + sraw[t*4+1] + sraw[t*4+2] + sraw[t*4+3] + sb[0];
    __syncthreads();

    // ---- LN + softmax per window ----
    if (t < 28) {
        int wr = t / 7, wc = t % 7;
        float sc[25];
#pragma unroll
        for (int a = 0; a < 5; a++)
#pragma unroll
            for (int c = 0; c < 5; c++) sc[a*5+c] = sfin[(wr+a)*11 + wc + c];
        float mu = 0.f;
#pragma unroll
        for (int k = 0; k < 25; k++) mu += sc[k];
        mu *= (1.f/25.f);
        float var = 0.f;
#pragma unroll
        for (int k = 0; k < 25; k++) { float d = sc[k]-mu; var += d*d; }
        var *= (1.f/25.f);
        float inv = rsqrtf(var + LNEPS);
        float e[25], mx = -1e30f;
#pragma unroll
        for (int k = 0; k < 25; k++) {
            float z = (sc[k]-mu)*inv*lnw[k] + lnb[k];
            e[k] = z; mx = fmaxf(mx, z);
        }
        float sum = 0.f;
#pragma unroll
        for (int k = 0; k < 25; k++) { e[k] = __expf(e[k]-mx); sum += e[k]; }
        float rs = 1.f/sum;
#pragma unroll
        for (int k = 0; k < 25; k++) wgt[t][k] = e[k]*rs;
    }
    __syncthreads();

    // ---- pass 2: aggregate all 28 windows from smem ----
    float4 acc[4][7];
#pragma unroll
    for (int wr = 0; wr < 4; wr++)
#pragma unroll
        for (int wc = 0; wc < 7; wc++) acc[wr][wc] = make_float4(0.f,0.f,0.f,0.f);

#pragma unroll
    for (int ki = 0; ki < 8; ki++) {
#pragma unroll
        for (int kj = 0; kj < 11; kj++) {
            int row = ki*11 + kj;
            float2 p0 = __half22float2(sx[row*256 + 2*t]);
            float2 p1 = __half22float2(sx[row*256 + 2*t + 1]);
#pragma unroll
            for (int wr = 0; wr < 4; wr++) {
                if (ki - wr < 0 || ki - wr > 4) continue;
#pragma unroll
                for (int wc = 0; wc < 7; wc++) {
                    if (kj - wc < 0 || kj - wc > 4) continue;
                    float wk = wgt[wr*7 + wc][(ki-wr)*5 + (kj-wc)];
                    acc[wr][wc].x += wk*p0.x; acc[wr][wc].y += wk*p0.y;
                    acc[wr][wc].z += wk*p1.x; acc[wr][wc].w += wk*p1.y;
                }
            }
        }
    }

#pragma unroll
    for (int wr = 0; wr < 4; wr++)
#pragma unroll
        for (int wc = 0; wc < 7; wc++) {
            int win = (n*HH + hh0 + wr)*WWN + ww0 + wc;
            size_t base = (size_t)win*CDIM + t*4;
            __half2 H0; H0.x = __float2half(acc[wr][wc].x); H0.y = __float2half(acc[wr][wc].y);
            __half2 H1; H1.x = __float2half(acc[wr][wc].z); H1.y = __float2half(acc[wr][wc].w);
            *(__half2*)(g_xa_h + base)     = H0;
            *(__half2*)(g_xa_h + base + 2) = H1;
        }
}

// ---------------------------------------------------------------------------
// K3: plain fp16 HMMA GEMM. CTA 128x64, KCH=64, SW128 swizzle, 3-stage
//     cp.async, 8 warps (32x32 warp tile), 3 CTAs/SM -> single wave.
// ---------------------------------------------------------------------------
#define BM 128
#define BN 64
#define KCH 64
#define NCH (CDIM/KCH)            // 8
#define ATILE_B (BM*128)          // 16384
#define BTILE_B (BN*128)          // 8192
#define STAGE_B (ATILE_B + BTILE_B)   // 24576
#define NSTG 3
#define DSMEM_B (NSTG*STAGE_B)    // 73728 >= epi 33280

__global__ __launch_bounds__(256, 3)
void hmma_gemm_kernel(const float* __restrict__ pb, float* __restrict__ out) {
    extern __shared__ char dsm[];
    const int tid = threadIdx.x, wid = tid >> 5, lane = tid & 31;
    const int bm = blockIdx.x * BM, bn = blockIdx.y * BN;
    const int m_org = (wid & 3) * 32;
    const int n_org = (wid >> 2) * 32;
    const int quad = lane >> 3, rq = lane & 7;

    float acc[2][4][4];
#pragma unroll
    for (int a = 0; a < 2; a++)
#pragma unroll
        for (int b = 0; b < 4; b++)
#pragma unroll
            for (int c = 0; c < 4; c++) acc[a][b][c] = 0.f;

    auto ISSUE = [&](int ck) {
        if (ck < NCH) {
            const int k0 = ck * KCH;
            char* buf = dsm + (ck % NSTG) * STAGE_B;
#pragma unroll
            for (int i = 0; i < 6; i++) {
                int idx = tid + i*256;             // 0..1535
                if (idx < 1024) {
                    int r = idx >> 3, j = idx & 7;
                    uint32_t off = (uint32_t)(r*128 + j*16);
                    off ^= (off >> 3) & 0x70;
                    cpasync16(s2u(buf + off),
                              g_xa_h + (size_t)(bm + r)*CDIM + k0 + j*8);
                } else {
                    int c = idx - 1024, r = c >> 3, j = c & 7;
                    uint32_t off = (uint32_t)(r*128 + j*16);
                    off ^= (off >> 3) & 0x70;
                    cpasync16(s2u(buf + ATILE_B + off),
                              g_pw_h + (size_t)(bn + r)*CDIM + k0 + j*8);
                }
            }
        }
        CP_COMMIT();
    };

    ISSUE(0);
    ISSUE(1);
    for (int ck = 0; ck < NCH; ck++) {
        char* buf = dsm + (ck % NSTG) * STAGE_B;
        CP_WAIT1();
        __syncthreads();
        ISSUE(ck + 2);

        const uint32_t abase = s2u(buf);
        const uint32_t bbase = s2u(buf + ATILE_B);
#pragma unroll
        for (int ks = 0; ks < 4; ks++) {
            const int jA = ks * 2;
            uint32_t ah[2][4];
#pragma unroll
            for (int mi = 0; mi < 2; mi++) {
                int row = m_org + mi*16 + rq + ((quad & 1) << 3);
                int jh = jA + (quad >> 1);
                uint32_t o = (uint32_t)(row*128 + jh*16); o ^= (o >> 3) & 0x70;
                ldmx4(ah[mi], abase + o);
            }
            uint32_t bh[2][4];
#pragma unroll
            for (int nb = 0; nb < 2; nb++) {
                int row = n_org + nb*16 + rq + ((quad >> 1) << 3);
                int jh = jA + (quad & 1);
                uint32_t o = (uint32_t)(row*128 + jh*16); o ^= (o >> 3) & 0x70;
                ldmx4(bh[nb], bbase + o);
            }
#pragma unroll
            for (int mi = 0; mi < 2; mi++)
#pragma unroll
                for (int nj = 0; nj < 4; nj++)
                    mma16816(acc[mi][nj], ah[mi], &bh[nj >> 1][(nj & 1) * 2]);
        }
        __syncthreads();
    }

    // epilogue: transpose through smem for coalesced (o-major) global stores
    float* cs = (float*)dsm;
#pragma unroll
    for (int mi = 0; mi < 2; mi++)
#pragma unroll
        for (int nj = 0; nj < 4; nj++) {
            int row = m_org + mi*16 + (lane >> 2);
            int col = n_org + nj*8 + 2*(lane & 3);
            cs[row*65 + col]       = acc[mi][nj][0];
            cs[row*65 + col + 1]   = acc[mi][nj][1];
            cs[(row+8)*65 + col]   = acc[mi][nj][2];
            cs[(row+8)*65 + col+1] = acc[mi][nj][3];
        }
    __syncthreads();
#pragma unroll 4
    for (int it = 0; it < 32; it++) {
        int linear = it*256 + tid;
        int col = linear >> 7, row = linear & 127;
        int m = bm + row, o = bn + col;
        int nimg = m / PIX_PER_IMG;
        int rem  = m - nimg * PIX_PER_IMG;
        out[(size_t)nimg*ODIM*PIX_PER_IMG + (size_t)o*PIX_PER_IMG + rem] =
            cs[row*65 + col] + __ldg(pb + o);
    }
}

// ---------------------------------------------------------------------------
extern "C" void kernel_launch(void* const* d_in, const int* in_sizes, int n_in,
                              void* d_out, int out_size) {
    const float* x   = (const float*)d_in[0];
    const float* pw  = (const float*)d_in[1];
    const float* pb  = (const float*)d_in[2];
    const float* sw  = (const float*)d_in[3];
    const float* sb  = (const float*)d_in[4];
    const float* lnw = (const float*)d_in[5];
    const float* lnb = (const float*)d_in[6];
    float* out = (float*)d_out;

    cudaFuncSetAttribute(fused_attn_kernel,
                         cudaFuncAttributeMaxDynamicSharedMemorySize, FUSED_SMEM);
    cudaFuncSetAttribute(hmma_gemm_kernel,
                         cudaFuncAttributeMaxDynamicSharedMemorySize, DSMEM_B);

    prep_w_kernel<<<(ODIM*CDIM)/1024, 256>>>(pw);
    fused_attn_kernel<<<NIMG*7*4, 128, FUSED_SMEM>>>(x, sw, sb, lnw, lnb);
    dim3 grid(NWIN/BM /*49*/, ODIM/BN /*8*/);
    hmma_gemm_kernel<<<grid, 256, DSMEM_B>>>(pb, out);
}